// round 4
// baseline (speedup 1.0000x reference)
#include <cuda_runtime.h>
#include <cuda_bf16.h>

// DWT_1D: lo/hi[n,c,k] = sum_{j=0..7} tap[j] * x[n,c, 2k+j-3], zero outside [0,SEQ)
// x: (16,64,8192) f32; out: lo (16,64,4096) then hi (16,64,4096), f32.
// Taps read from banded matrices: matrix_low[2, 1+j] == REC_LO[j].
//
// Each thread: 8 outputs (k = 8g..8g+7). Loads its 4 aligned float4 (16 floats,
// zero redundancy); halo float4s come from neighbor lanes via shuffle. Warp-edge
// lanes (0, 31) load their halo directly (predicated), so only 2 extra loads/warp.

namespace {
constexpr int SEQ  = 8192;
constexpr int KOUT = 4096;
constexpr int NC   = 16 * 64;         // 1024 rows
constexpr int TPB  = 256;
constexpr int GPR  = KOUT / 8;        // 512 groups per row (warp-aligned: 16 warps/row)
constexpr int S4   = SEQ / 4;         // 2048 float4 per row
}

__global__ __launch_bounds__(TPB)
void dwt1d_kernel(const float4* __restrict__ x4,
                  const float* __restrict__ mlo,
                  const float* __restrict__ mhi,
                  float* __restrict__ out)
{
    const int u    = blockIdx.x * TPB + threadIdx.x;   // 0 .. NC*GPR-1
    const int row  = u >> 9;                           // /512
    const int g    = u & (GPR - 1);                    // group within row
    const int lane = threadIdx.x & 31;

    const float4* __restrict__ xr = x4 + (size_t)row * S4;
    const int j0 = 4 * g;

    // Core loads: exactly this thread's 16 floats, aligned, fully coalesced.
    float4 v0 = xr[j0 + 0];
    float4 v1 = xr[j0 + 1];
    float4 v2 = xr[j0 + 2];
    float4 v3 = xr[j0 + 3];

    // Warp-edge halo loads (only lanes 0 and 31; row ends -> zero).
    float4 vE = make_float4(0.f, 0.f, 0.f, 0.f);
    if (lane == 0) {
        if (g != 0) vE = xr[j0 - 1];
    } else if (lane == 31) {
        if (j0 + 4 < S4) vE = xr[j0 + 4];
    }

    // Filter taps from the banded matrices (row 2, cols 1..8) — uniform broadcast.
    float h[8], gg[8];
    #pragma unroll
    for (int j = 0; j < 8; ++j) {
        h[j]  = __ldg(&mlo[2 * SEQ + 1 + j]);
        gg[j] = __ldg(&mhi[2 * SEQ + 1 + j]);
    }

    // Halo exchange via shuffle: vL = lane-1's v3, vR = lane+1's v0.
    float4 vL, vR;
    vL.x = __shfl_up_sync(0xffffffffu, v3.x, 1);
    vL.y = __shfl_up_sync(0xffffffffu, v3.y, 1);
    vL.z = __shfl_up_sync(0xffffffffu, v3.z, 1);
    vL.w = __shfl_up_sync(0xffffffffu, v3.w, 1);
    vR.x = __shfl_down_sync(0xffffffffu, v0.x, 1);
    vR.y = __shfl_down_sync(0xffffffffu, v0.y, 1);
    vR.z = __shfl_down_sync(0xffffffffu, v0.z, 1);
    vR.w = __shfl_down_sync(0xffffffffu, v0.w, 1);
    if (lane == 0)  vL = vE;
    if (lane == 31) vR = vE;

    // Window w[m] = x[16g - 4 + m], m = 0..23.
    float w[24] = { vL.x, vL.y, vL.z, vL.w,
                    v0.x, v0.y, v0.z, v0.w,
                    v1.x, v1.y, v1.z, v1.w,
                    v2.x, v2.y, v2.z, v2.w,
                    v3.x, v3.y, v3.z, v3.w,
                    vR.x, vR.y, vR.z, vR.w };

    // Outputs k = 8g + p: x[16g + 2p - 3 + j] = w[2p + 1 + j].
    float lo[8], hi[8];
    #pragma unroll
    for (int p = 0; p < 8; ++p) {
        float a = 0.f, b = 0.f;
        #pragma unroll
        for (int j = 0; j < 8; ++j) {
            const float xv = w[2*p + 1 + j];
            a = fmaf(h[j],  xv, a);
            b = fmaf(gg[j], xv, b);
        }
        lo[p] = a; hi[p] = b;
    }

    float4* __restrict__ lo4 = reinterpret_cast<float4*>(out + (size_t)row * KOUT) + 2 * g;
    float4* __restrict__ hi4 = reinterpret_cast<float4*>(out + (size_t)NC * KOUT + (size_t)row * KOUT) + 2 * g;
    lo4[0] = make_float4(lo[0], lo[1], lo[2], lo[3]);
    lo4[1] = make_float4(lo[4], lo[5], lo[6], lo[7]);
    hi4[0] = make_float4(hi[0], hi[1], hi[2], hi[3]);
    hi4[1] = make_float4(hi[4], hi[5], hi[6], hi[7]);
}

extern "C" void kernel_launch(void* const* d_in, const int* in_sizes, int n_in,
                              void* d_out, int out_size)
{
    const float4* x  = (const float4*)d_in[0];
    const float* mlo = (const float*)d_in[1];
    const float* mhi = (const float*)d_in[2];
    float* out = (float*)d_out;

    dwt1d_kernel<<<(NC * GPR) / TPB, TPB>>>(x, mlo, mhi, out);
}

// round 6
// speedup vs baseline: 1.3172x; 1.3172x over previous
#include <cuda_runtime.h>
#include <cuda_bf16.h>

// DWT_1D: lo/hi[n,c,k] = sum_{j=0..7} tap[j] * x[n,c, 2k+j-3], zero outside [0,SEQ)
// x: (16,64,8192) f32; out: lo (16,64,4096) then hi (16,64,4096), f32.
// Taps read from banded matrices: matrix_low[2, 1+j] == REC_LO[j].
//
// Each thread: 8 outputs (k = 8g..8g+7), window = 6 aligned float4 loads.
// __launch_bounds__(TPB, 1) gives ptxas a full register budget (R2/R3 at 32 regs
// spilled the 40-float working set to local memory -> fake "L1-bound").

namespace {
constexpr int SEQ  = 8192;
constexpr int KOUT = 4096;
constexpr int NC   = 16 * 64;         // 1024 rows
constexpr int TPB  = 256;
constexpr int GPR  = KOUT / 8;        // 512 output-groups (of 8) per row
constexpr int S4   = SEQ / 4;         // 2048 float4 per row
}

__global__ __launch_bounds__(TPB, 1)
void dwt1d_kernel(const float4* __restrict__ x4,
                  const float* __restrict__ mlo,
                  const float* __restrict__ mhi,
                  float* __restrict__ out)
{
    const int u   = blockIdx.x * TPB + threadIdx.x;   // 0 .. NC*GPR-1
    const int row = u >> 9;                            // /512
    const int gl  = u & (GPR - 1);                     // group within row

    const float4* __restrict__ xr = x4 + (size_t)row * S4;

    // Window: x[16gl-4 .. 16gl+19] as 6 float4 loads (idx 4gl-1 .. 4gl+4).
    // Only the first/last group of a row can go out of range.
    float w[24];
    const int j0 = 4 * gl - 1;
    #pragma unroll
    for (int i = 0; i < 6; ++i) {
        const int j = j0 + i;
        float4 v;
        if (j >= 0 && j < S4) v = xr[j];
        else                  v = make_float4(0.f, 0.f, 0.f, 0.f);
        w[4*i + 0] = v.x; w[4*i + 1] = v.y; w[4*i + 2] = v.z; w[4*i + 3] = v.w;
    }

    // Filter taps from the banded matrices (row 2, cols 1..8) — uniform broadcast.
    float h[8], g[8];
    #pragma unroll
    for (int j = 0; j < 8; ++j) {
        h[j] = __ldg(&mlo[2 * SEQ + 1 + j]);
        g[j] = __ldg(&mhi[2 * SEQ + 1 + j]);
    }

    // Outputs k = 8gl + p, p = 0..7; input x[16gl + 2p - 3 + j] = w[2p + 1 + j].
    float lo[8], hi[8];
    #pragma unroll
    for (int p = 0; p < 8; ++p) {
        float a = 0.f, b = 0.f;
        #pragma unroll
        for (int j = 0; j < 8; ++j) {
            const float xv = w[2*p + 1 + j];
            a = fmaf(h[j], xv, a);
            b = fmaf(g[j], xv, b);
        }
        lo[p] = a; hi[p] = b;
    }

    float4* __restrict__ lo4 = reinterpret_cast<float4*>(out + (size_t)row * KOUT) + 2 * gl;
    float4* __restrict__ hi4 = reinterpret_cast<float4*>(out + (size_t)NC * KOUT + (size_t)row * KOUT) + 2 * gl;
    lo4[0] = make_float4(lo[0], lo[1], lo[2], lo[3]);
    lo4[1] = make_float4(lo[4], lo[5], lo[6], lo[7]);
    hi4[0] = make_float4(hi[0], hi[1], hi[2], hi[3]);
    hi4[1] = make_float4(hi[4], hi[5], hi[6], hi[7]);
}

extern "C" void kernel_launch(void* const* d_in, const int* in_sizes, int n_in,
                              void* d_out, int out_size)
{
    const float4* x  = (const float4*)d_in[0];
    const float* mlo = (const float*)d_in[1];
    const float* mhi = (const float*)d_in[2];
    float* out = (float*)d_out;

    dwt1d_kernel<<<(NC * GPR) / TPB, TPB>>>(x, mlo, mhi, out);
}

// round 8
// speedup vs baseline: 1.7346x; 1.3170x over previous
#include <cuda_runtime.h>
#include <cuda_bf16.h>

// DWT_1D via polyphase: lo/hi[n,c,k] = sum_j tap[j]*x[n,c,2k+j-3].
// Split x into xe[i]=x[2i], xo[i]=x[2i+1]:
//   lo[k] = h0*xo[k-2]+h2*xo[k-1]+h4*xo[k]+h6*xo[k+1]
//         + h1*xe[k-1]+h3*xe[k]  +h5*xe[k+1]+h7*xe[k+2]   (hi same with g taps)
// Both phases are stride-1 4-tap convs -> every gmem/smem access is lane-contiguous
// (the R1..R6 kernels all lost 4x L1 wavefronts to 64B lane striding).
//
// One block per row. Stage + deinterleave into smem, then each thread computes
// 4 consecutive outputs from conflict-free float4 smem reads.

namespace {
constexpr int SEQ  = 8192;
constexpr int KOUT = 4096;
constexpr int NC   = 16 * 64;          // 1024 rows
constexpr int TPB  = 256;
constexpr int NE   = 4104;             // xe_s: [0..3]=0, [4..4099]=xe[0..4095], [4100..4103]=0
constexpr int NO   = 4104;             // xo_s: [0..1]=0, [2..4097]=xo[0..4095], [4098..4103]=0
}

__global__ __launch_bounds__(TPB, 1)
void dwt1d_kernel(const float4* __restrict__ x4,
                  const float* __restrict__ mlo,
                  const float* __restrict__ mhi,
                  float* __restrict__ out)
{
    __shared__ alignas(16) float xe_s[NE];   // xe_s[j] = xe[j-4]
    __shared__ alignas(16) float xo_s[NO];   // xo_s[j] = xo[j-2]

    const int row = blockIdx.x;
    const int tid = threadIdx.x;

    // Zero the pad slots.
    if (tid < 4) { xe_s[tid] = 0.f; xe_s[4100 + tid] = 0.f; }
    else if (tid < 6)  { xo_s[tid - 4] = 0.f; }
    else if (tid < 12) { xo_s[4098 + (tid - 6)] = 0.f; }

    // Stage + deinterleave: contiguous LDG.128, conflict-free STS.64.
    {
        const float4* __restrict__ xr = x4 + (size_t)row * (SEQ / 4);
        float2* __restrict__ xe2 = reinterpret_cast<float2*>(xe_s);
        float2* __restrict__ xo2 = reinterpret_cast<float2*>(xo_s);
        #pragma unroll
        for (int i = 0; i < SEQ / 4 / TPB; ++i) {         // 8 iters
            const int f = tid + i * TPB;
            float4 v = xr[f];
            xe2[f + 2] = make_float2(v.x, v.z);           // xe[2f],xe[2f+1] -> idx 2f+4
            xo2[f + 1] = make_float2(v.y, v.w);           // xo[2f],xo[2f+1] -> idx 2f+2
        }
    }

    // Taps from the banded matrices (row 2, cols 1..8) — uniform broadcast.
    float h[8], g[8];
    #pragma unroll
    for (int j = 0; j < 8; ++j) {
        h[j] = __ldg(&mlo[2 * SEQ + 1 + j]);
        g[j] = __ldg(&mhi[2 * SEQ + 1 + j]);
    }

    __syncthreads();

    const float4* __restrict__ xe4 = reinterpret_cast<const float4*>(xe_s);
    const float4* __restrict__ xo4 = reinterpret_cast<const float4*>(xo_s);
    float4* __restrict__ lo4 = reinterpret_cast<float4*>(out + (size_t)row * KOUT);
    float4* __restrict__ hi4 = reinterpret_cast<float4*>(out + (size_t)NC * KOUT + (size_t)row * KOUT);

    #pragma unroll
    for (int it = 0; it < KOUT / 4 / TPB; ++it) {         // 4 iters
        const int t = tid + it * TPB;                     // 0..1023; outputs k = 4t..4t+3

        // xo[4t-2 .. 4t+5]  (need 4t-2..4t+4)
        float4 o0 = xo4[t];
        float4 o1 = xo4[t + 1];
        // xe[4t-4 .. 4t+7]  (need 4t-1..4t+5)
        float4 e0 = xe4[t];
        float4 e1 = xe4[t + 1];
        float4 e2 = xe4[t + 2];

        const float o[8]  = { o0.x, o0.y, o0.z, o0.w, o1.x, o1.y, o1.z, o1.w };
        const float a[12] = { e0.x, e0.y, e0.z, e0.w, e1.x, e1.y, e1.z, e1.w,
                              e2.x, e2.y, e2.z, e2.w };

        float lo[4], hi[4];
        #pragma unroll
        for (int d = 0; d < 4; ++d) {
            // xo[k-2+i] = o[d+i],  xe[k-1+i] = a[d+3+i]
            float s0 = fmaf(h[0], o[d+0], h[1] * a[d+3]);
            s0 = fmaf(h[2], o[d+1], s0);
            s0 = fmaf(h[3], a[d+4], s0);
            s0 = fmaf(h[4], o[d+2], s0);
            s0 = fmaf(h[5], a[d+5], s0);
            s0 = fmaf(h[6], o[d+3], s0);
            s0 = fmaf(h[7], a[d+6], s0);
            lo[d] = s0;

            float s1 = fmaf(g[0], o[d+0], g[1] * a[d+3]);
            s1 = fmaf(g[2], o[d+1], s1);
            s1 = fmaf(g[3], a[d+4], s1);
            s1 = fmaf(g[4], o[d+2], s1);
            s1 = fmaf(g[5], a[d+5], s1);
            s1 = fmaf(g[6], o[d+3], s1);
            s1 = fmaf(g[7], a[d+6], s1);
            hi[d] = s1;
        }

        lo4[t] = make_float4(lo[0], lo[1], lo[2], lo[3]);
        hi4[t] = make_float4(hi[0], hi[1], hi[2], hi[3]);
    }
}

extern "C" void kernel_launch(void* const* d_in, const int* in_sizes, int n_in,
                              void* d_out, int out_size)
{
    const float4* x  = (const float4*)d_in[0];
    const float* mlo = (const float*)d_in[1];
    const float* mhi = (const float*)d_in[2];
    float* out = (float*)d_out;

    dwt1d_kernel<<<NC, TPB>>>(x, mlo, mhi, out);
}

// round 10
// speedup vs baseline: 1.7694x; 1.0201x over previous
#include <cuda_runtime.h>
#include <cuda_bf16.h>

// DWT_1D via polyphase: lo/hi[n,c,k] = sum_j tap[j]*x[n,c,2k+j-3].
//   lo[k] = h0*xo[k-2]+h2*xo[k-1]+h4*xo[k]+h6*xo[k+1]
//         + h1*xe[k-1]+h3*xe[k]+h5*xe[k+1]+h7*xe[k+2]
//   hi[k] = h7*xo[k-2]-h6*xe[k-1]+h5*xo[k-1]-h4*xe[k]
//         + h3*xo[k]-h2*xe[k+1]+h1*xo[k+1]-h0*xe[k+2]
// (REC_HI[j] = (-1)^j REC_LO[7-j], bit-exact in the reference constants ->
//  hi uses the same 8 tap registers with free FFMA operand negation.)
// All gmem/smem accesses lane-contiguous. Pad=2 on both phases so each window
// spans exactly 2 float4 smem reads (4 LDS.128 per 8 outputs).

namespace {
constexpr int SEQ  = 8192;
constexpr int KOUT = 4096;
constexpr int NC   = 16 * 64;          // 1024 rows
constexpr int TPB  = 256;
constexpr int NP   = 4104;             // per-phase smem: [0..1]=0, [2..4097]=data, [4098..4103]=0
}

__global__ __launch_bounds__(TPB, 5)
void dwt1d_kernel(const float4* __restrict__ x4,
                  const float* __restrict__ mlo,
                  const float* __restrict__ mhi,
                  float* __restrict__ out)
{
    __shared__ alignas(16) float xe_s[NP];   // xe_s[j] = xe[j-2]
    __shared__ alignas(16) float xo_s[NP];   // xo_s[j] = xo[j-2]

    const int row = blockIdx.x;
    const int tid = threadIdx.x;

    // Zero pad slots (front 2, back 6, both phases).
    if (tid < 2)       { xe_s[tid] = 0.f;        xo_s[tid] = 0.f; }
    else if (tid < 8)  { xe_s[4096 + tid] = 0.f; xo_s[4096 + tid] = 0.f; }

    // Stage + deinterleave: contiguous LDG.128, conflict-free STS.64.
    {
        const float4* __restrict__ xr = x4 + (size_t)row * (SEQ / 4);
        float2* __restrict__ xe2 = reinterpret_cast<float2*>(xe_s);
        float2* __restrict__ xo2 = reinterpret_cast<float2*>(xo_s);
        #pragma unroll
        for (int i = 0; i < SEQ / 4 / TPB; ++i) {         // 8 iters
            const int f = tid + i * TPB;
            float4 v = xr[f];
            xe2[f + 1] = make_float2(v.x, v.z);           // xe[2f],xe[2f+1] -> j=2f+2
            xo2[f + 1] = make_float2(v.y, v.w);           // xo[2f],xo[2f+1] -> j=2f+2
        }
    }

    // Low-pass taps only (hi derived); row 2, cols 1..8 of the banded matrix.
    float h[8];
    #pragma unroll
    for (int j = 0; j < 8; ++j) h[j] = __ldg(&mlo[2 * SEQ + 1 + j]);

    __syncthreads();

    const float4* __restrict__ xe4 = reinterpret_cast<const float4*>(xe_s);
    const float4* __restrict__ xo4 = reinterpret_cast<const float4*>(xo_s);
    float4* __restrict__ lo4 = reinterpret_cast<float4*>(out + (size_t)row * KOUT);
    float4* __restrict__ hi4 = reinterpret_cast<float4*>(out + (size_t)NC * KOUT + (size_t)row * KOUT);

    #pragma unroll
    for (int it = 0; it < KOUT / 4 / TPB; ++it) {         // 4 iters
        const int t = tid + it * TPB;                     // outputs k = 4t..4t+3

        // o[m] = xo[4t-2+m], e[m] = xe[4t-2+m], m = 0..7 (2 float4 loads each).
        float4 o0 = xo4[t];
        float4 o1 = xo4[t + 1];
        float4 e0 = xe4[t];
        float4 e1 = xe4[t + 1];
        const float o[8] = { o0.x, o0.y, o0.z, o0.w, o1.x, o1.y, o1.z, o1.w };
        const float e[8] = { e0.x, e0.y, e0.z, e0.w, e1.x, e1.y, e1.z, e1.w };

        float lo[4], hi[4];
        #pragma unroll
        for (int d = 0; d < 4; ++d) {
            // lo: h taps forward
            float s0 = fmaf(h[0], o[d+0], h[1] * e[d+1]);
            s0 = fmaf(h[2], o[d+1], s0);
            s0 = fmaf(h[3], e[d+2], s0);
            s0 = fmaf(h[4], o[d+2], s0);
            s0 = fmaf(h[5], e[d+3], s0);
            s0 = fmaf(h[6], o[d+3], s0);
            s0 = fmaf(h[7], e[d+4], s0);
            lo[d] = s0;
            // hi: reversed/alternating-sign h taps (free FFMA negation)
            float s1 = fmaf(h[7], o[d+0], h[6] * (-e[d+1]));
            s1 = fmaf(h[5], o[d+1], s1);
            s1 = fmaf(h[4], -e[d+2], s1);
            s1 = fmaf(h[3], o[d+2], s1);
            s1 = fmaf(h[2], -e[d+3], s1);
            s1 = fmaf(h[1], o[d+3], s1);
            s1 = fmaf(h[0], -e[d+4], s1);
            hi[d] = s1;
        }

        lo4[t] = make_float4(lo[0], lo[1], lo[2], lo[3]);
        hi4[t] = make_float4(hi[0], hi[1], hi[2], hi[3]);
    }
}

extern "C" void kernel_launch(void* const* d_in, const int* in_sizes, int n_in,
                              void* d_out, int out_size)
{
    const float4* x  = (const float4*)d_in[0];
    const float* mlo = (const float*)d_in[1];
    const float* mhi = (const float*)d_in[2];
    float* out = (float*)d_out;

    dwt1d_kernel<<<NC, TPB>>>(x, mlo, mhi, out);
}